// round 10
// baseline (speedup 1.0000x reference)
#include <cuda_runtime.h>
#include <cuda_fp16.h>
#include <cstdint>

#define MAXN 100000
#define MAXE 1250000
#define DH   64
#define CC   40

// ---------------- device scratch (static; no runtime allocation) -------------
__device__ __align__(16) float g_dis[MAXN];
__device__ int   g_deg[MAXN];
__device__ int   g_rowptr[MAXN + 1];
__device__ int   g_cur[MAXN];
__device__ int   g_csr[MAXE];
__device__ volatile unsigned long long g_pack[512];   // lookback scan state
__device__ int   g_is64;
__device__ __align__(16) float   g_y  [(size_t)MAXN * DH];
__device__ __align__(16) float   g_h1 [(size_t)MAXN * DH];
__device__ __align__(16) __half2 g_xh [(size_t)MAXN * 32];  // dis*x   (fp16)
__device__ __align__(16) __half2 g_h1h[(size_t)MAXN * 32];  // dis*h1  (fp16)

// ---------------- helpers ----------------------------------------------------
__device__ __forceinline__ int edge_at(const void* ei, long long pos) {
    if (g_is64) return (int)((const long long*)ei)[pos];
    return ((const int*)ei)[pos];
}

// zero deg + scan state + int64/int32 detection, one kernel
__global__ void k_init(const void* ei, int n) {
    int i = blockIdx.x * blockDim.x + threadIdx.x;
    if (i < n) g_deg[i] = 0;
    if (i < 512) g_pack[i] = 0ull;
    if (i == 0) {
        const long long* p = (const long long*)ei;
        int ok = 1;
        #pragma unroll
        for (int k = 0; k < 8; k++) {
            long long v = p[k];
            if (v < 0 || v >= (long long)n) ok = 0;
        }
        g_is64 = ok;
    }
}

__global__ void k_count(const void* ei, int E) {
    int e = blockIdx.x * blockDim.x + threadIdx.x;
    if (e < E) atomicAdd(&g_deg[edge_at(ei, (long long)E + e)], 1);
}

// ---- single-pass exclusive scan (decoupled lookback) -> rowptr/cur/dis ------
#define FLAG_AGG (1ull << 62)
#define FLAG_PRE (2ull << 62)

__global__ void k_scan(int n) {
    __shared__ int s[256];
    __shared__ int s_prefix;
    const int b = blockIdx.x;
    const int t = threadIdx.x;
    const int i = b * 256 + t;
    const int v = (i < n) ? g_deg[i] : 0;

    s[t] = v;
    __syncthreads();
    #pragma unroll
    for (int off = 1; off < 256; off <<= 1) {
        int add = (t >= off) ? s[t - off] : 0;
        __syncthreads();
        s[t] += add;
        __syncthreads();
    }

    if (t == 0) {
        int total = s[255];
        if (b == 0) {
            g_pack[0] = FLAG_PRE | (unsigned long long)(unsigned)total;
            s_prefix = 0;
        } else {
            g_pack[b] = FLAG_AGG | (unsigned long long)(unsigned)total;
            int prefix = 0;
            int j = b - 1;
            while (true) {
                unsigned long long p;
                while ((p = g_pack[j]) == 0ull) { /* spin */ }
                int val = (int)(p & 0xFFFFFFFFull);
                prefix += val;
                if (p & FLAG_PRE) break;
                j--;
            }
            g_pack[b] = FLAG_PRE | (unsigned long long)(unsigned)(prefix + total);
            s_prefix = prefix;
        }
    }
    __syncthreads();

    if (i < n) {
        int excl = s_prefix + s[t] - v;
        g_rowptr[i] = excl;
        g_cur[i]    = excl;
        g_dis[i]    = rsqrtf((float)(v + 1));     // +1 = self-loop
        if (i == n - 1) g_rowptr[n] = excl + v;
    }
}

__global__ void k_fill(const void* ei, int E) {
    int e = blockIdx.x * blockDim.x + threadIdx.x;
    if (e < E) {
        int r = edge_at(ei, (long long)e);
        int c = edge_at(ei, (long long)E + e);
        int pos = atomicAdd(&g_cur[c], 1);
        g_csr[pos] = r;
    }
}

// -------- prescale: xh[i] = half2(dis_node * x[i]) ----------------------------
__global__ void k_prescale(const float* __restrict__ x, int n) {
    int i = blockIdx.x * blockDim.x + threadIdx.x;     // over n*32 half2 slots
    if (i >= n * 32) return;
    int node = i >> 5;
    float d = g_dis[node];
    float2 v = ((const float2*)x)[i];
    g_xh[i] = __floats2half2_rn(d * v.x, d * v.y);
}

// -------- aggregation: y_i = dis_i*self_i (fp32) + sum_nbr prescaled fp16 -----
// warp per node, lane owns one half2 (row = 128B, sector-aligned). unroll 8.
__global__ void k_agg(const __half2* __restrict__ Hh, const float* __restrict__ self,
                      float* __restrict__ y, int n)
{
    int w = (blockIdx.x * blockDim.x + threadIdx.x) >> 5;
    int lane = threadIdx.x & 31;
    if (w >= n) return;

    float  dw = g_dis[w];
    float2 v0 = ((const float2*)self)[(size_t)w * 32 + lane];
    float2 acc = make_float2(dw * v0.x, dw * v0.y);

    int p   = g_rowptr[w];
    int end = g_rowptr[w + 1];
    for (; p + 7 < end; p += 8) {
        int s0 = __ldg(&g_csr[p]);
        int s1 = __ldg(&g_csr[p + 1]);
        int s2 = __ldg(&g_csr[p + 2]);
        int s3 = __ldg(&g_csr[p + 3]);
        int s4 = __ldg(&g_csr[p + 4]);
        int s5 = __ldg(&g_csr[p + 5]);
        int s6 = __ldg(&g_csr[p + 6]);
        int s7 = __ldg(&g_csr[p + 7]);
        __half2 a0 = Hh[(size_t)s0 * 32 + lane];
        __half2 a1 = Hh[(size_t)s1 * 32 + lane];
        __half2 a2 = Hh[(size_t)s2 * 32 + lane];
        __half2 a3 = Hh[(size_t)s3 * 32 + lane];
        __half2 a4 = Hh[(size_t)s4 * 32 + lane];
        __half2 a5 = Hh[(size_t)s5 * 32 + lane];
        __half2 a6 = Hh[(size_t)s6 * 32 + lane];
        __half2 a7 = Hh[(size_t)s7 * 32 + lane];
        float2 f0 = __half22float2(a0);
        float2 f1 = __half22float2(a1);
        float2 f2 = __half22float2(a2);
        float2 f3 = __half22float2(a3);
        float2 f4 = __half22float2(a4);
        float2 f5 = __half22float2(a5);
        float2 f6 = __half22float2(a6);
        float2 f7 = __half22float2(a7);
        acc.x += ((f0.x + f1.x) + (f2.x + f3.x)) + ((f4.x + f5.x) + (f6.x + f7.x));
        acc.y += ((f0.y + f1.y) + (f2.y + f3.y)) + ((f4.y + f5.y) + (f6.y + f7.y));
    }
    for (; p < end; p++) {
        int s0 = __ldg(&g_csr[p]);
        float2 f = __half22float2(Hh[(size_t)s0 * 32 + lane]);
        acc.x += f.x;
        acc.y += f.y;
    }
    ((float2*)y)[(size_t)w * 32 + lane] = acc;
}

// ------------- GEMM+finish: h1 = relu(dis*(y@W)+b); also h1h = half(dis*h1) ---
__global__ void k_gemm_h(const float* __restrict__ Y, const float* __restrict__ W,
                         const float* __restrict__ bias, float* __restrict__ out, int n)
{
    __shared__ float  Xs[64 * 64];
    __shared__ float4 Ws[64 * 16];

    const int tx = threadIdx.x, ty = threadIdx.y;
    const int tid = ty * 16 + tx;

    const float4* Wv = (const float4*)W;
    #pragma unroll
    for (int i = 0; i < 4; i++) Ws[tid + i * 256] = Wv[tid + i * 256];

    const int r0 = blockIdx.x * 64;
    #pragma unroll
    for (int i = 0; i < 4; i++) {
        int idx = tid + i * 256;
        int rr = idx >> 4, cc = idx & 15;
        int gr = r0 + rr;
        float4 v = make_float4(0.f, 0.f, 0.f, 0.f);
        if (gr < n) v = ((const float4*)(Y + (size_t)gr * DH))[cc];
        *(float4*)&Xs[rr * 64 + cc * 4] = v;
    }
    __syncthreads();

    float4 acc[4];
    #pragma unroll
    for (int i = 0; i < 4; i++) acc[i] = make_float4(0.f, 0.f, 0.f, 0.f);

    #pragma unroll
    for (int k4 = 0; k4 < 16; k4++) {
        float4 xv[4];
        #pragma unroll
        for (int i = 0; i < 4; i++)
            xv[i] = *(const float4*)&Xs[(ty * 4 + i) * 64 + k4 * 4];
        #pragma unroll
        for (int j = 0; j < 4; j++) {
            float4 w = Ws[(k4 * 4 + j) * 16 + tx];
            #pragma unroll
            for (int i = 0; i < 4; i++) {
                float xs = (j == 0) ? xv[i].x : (j == 1) ? xv[i].y : (j == 2) ? xv[i].z : xv[i].w;
                acc[i].x = fmaf(xs, w.x, acc[i].x);
                acc[i].y = fmaf(xs, w.y, acc[i].y);
                acc[i].z = fmaf(xs, w.z, acc[i].z);
                acc[i].w = fmaf(xs, w.w, acc[i].w);
            }
        }
    }

    float4 b = ((const float4*)bias)[tx];
    #pragma unroll
    for (int i = 0; i < 4; i++) {
        int gr = r0 + ty * 4 + i;
        if (gr >= n) continue;
        float s = g_dis[gr];
        float4 a = acc[i];
        a.x = fmaxf(fmaf(s, a.x, b.x), 0.f);
        a.y = fmaxf(fmaf(s, a.y, b.y), 0.f);
        a.z = fmaxf(fmaf(s, a.z, b.z), 0.f);
        a.w = fmaxf(fmaf(s, a.w, b.w), 0.f);
        ((float4*)(out + (size_t)gr * DH))[tx] = a;
        // prescaled fp16 copy for the hop-2 gather
        g_h1h[(size_t)gr * 32 + tx * 2]     = __floats2half2_rn(s * a.x, s * a.y);
        g_h1h[(size_t)gr * 32 + tx * 2 + 1] = __floats2half2_rn(s * a.z, s * a.w);
    }
}

// ---------------- fused classifier -------------------------------------------
// out = [ego | h1 | h2] @ W_cls + b_cls
//   ego = relu(x @ W_ego + b_ego)       (in-register from x tile)
//   h2  = relu(dis*(y2 @ Wc1) + b1)     (in-register from pre-aggregated y2)
__global__ void k_cls(const float* __restrict__ x, const float* __restrict__ h1,
                      const float* __restrict__ y2,
                      const float* __restrict__ Wego, const float* __restrict__ bego,
                      const float* __restrict__ Wc1,  const float* __restrict__ bc1,
                      const float* __restrict__ Wcls, const float* __restrict__ bcls,
                      float* __restrict__ out, int n)
{
    __shared__ float  Xs[64 * 68];     // 17408 B
    __shared__ float4 Wcs[192 * 10];   // 30720 B

    const int tx = threadIdx.x, ty = threadIdx.y;
    const int tid = ty * 16 + tx;
    const int r0 = blockIdx.x * 64;

    const float4* Wclsv = (const float4*)Wcls;
    #pragma unroll
    for (int i = tid; i < 1920; i += 256) Wcs[i] = Wclsv[i];

    float4 acc[4];
    #pragma unroll
    for (int i = 0; i < 4; i++) acc[i] = make_float4(0.f, 0.f, 0.f, 0.f);

    auto load_tile = [&](const float* S) {
        #pragma unroll
        for (int i = 0; i < 4; i++) {
            int idx = tid + i * 256;
            int rr = idx >> 4, cc = idx & 15;
            int gr = r0 + rr;
            float4 v = make_float4(0.f, 0.f, 0.f, 0.f);
            if (gr < n) v = ((const float4*)(S + (size_t)gr * DH))[cc];
            *(float4*)&Xs[rr * 68 + cc * 4] = v;
        }
    };

    auto transform = [&](const float* W, const float* bias, bool use_dis) {
        const float4* Wv = (const float4*)W;
        float4 t[4];
        #pragma unroll
        for (int i = 0; i < 4; i++) t[i] = make_float4(0.f, 0.f, 0.f, 0.f);
        #pragma unroll
        for (int k4 = 0; k4 < 16; k4++) {
            float4 xv[4];
            #pragma unroll
            for (int i = 0; i < 4; i++)
                xv[i] = *(const float4*)&Xs[(ty * 4 + i) * 68 + k4 * 4];
            #pragma unroll
            for (int j = 0; j < 4; j++) {
                float4 w = __ldg(&Wv[(k4 * 4 + j) * 16 + tx]);
                #pragma unroll
                for (int i = 0; i < 4; i++) {
                    float xs = (j == 0) ? xv[i].x : (j == 1) ? xv[i].y : (j == 2) ? xv[i].z : xv[i].w;
                    t[i].x = fmaf(xs, w.x, t[i].x);
                    t[i].y = fmaf(xs, w.y, t[i].y);
                    t[i].z = fmaf(xs, w.z, t[i].z);
                    t[i].w = fmaf(xs, w.w, t[i].w);
                }
            }
        }
        float4 b = __ldg(&((const float4*)bias)[tx]);
        __syncthreads();               // done reading old Xs
        #pragma unroll
        for (int i = 0; i < 4; i++) {
            int gr = r0 + ty * 4 + i;
            float s = 1.0f;
            if (use_dis) s = (gr < n) ? g_dis[gr] : 0.f;
            float4 a = t[i];
            a.x = fmaxf(fmaf(s, a.x, b.x), 0.f);
            a.y = fmaxf(fmaf(s, a.y, b.y), 0.f);
            a.z = fmaxf(fmaf(s, a.z, b.z), 0.f);
            a.w = fmaxf(fmaf(s, a.w, b.w), 0.f);
            *(float4*)&Xs[(ty * 4 + i) * 68 + tx * 4] = a;
        }
    };

    auto cls_accum = [&](int c) {
        if (tx < 10) {
            #pragma unroll
            for (int k4 = 0; k4 < 16; k4++) {
                float4 xv[4];
                #pragma unroll
                for (int i = 0; i < 4; i++)
                    xv[i] = *(const float4*)&Xs[(ty * 4 + i) * 68 + k4 * 4];
                #pragma unroll
                for (int j = 0; j < 4; j++) {
                    float4 w = Wcs[(c * 64 + k4 * 4 + j) * 10 + tx];
                    #pragma unroll
                    for (int i = 0; i < 4; i++) {
                        float xs = (j == 0) ? xv[i].x : (j == 1) ? xv[i].y : (j == 2) ? xv[i].z : xv[i].w;
                        acc[i].x = fmaf(xs, w.x, acc[i].x);
                        acc[i].y = fmaf(xs, w.y, acc[i].y);
                        acc[i].z = fmaf(xs, w.z, acc[i].z);
                        acc[i].w = fmaf(xs, w.w, acc[i].w);
                    }
                }
            }
        }
    };

    // phase 0: ego = relu(x @ Wego + bego)
    load_tile(x);
    __syncthreads();
    transform(Wego, bego, false);
    __syncthreads();
    cls_accum(0);
    __syncthreads();

    // phase 1: h1 (materialized)
    load_tile(h1);
    __syncthreads();
    cls_accum(1);
    __syncthreads();

    // phase 2: h2 = relu(dis*(y2 @ Wc1) + b1)
    load_tile(y2);
    __syncthreads();
    transform(Wc1, bc1, true);
    __syncthreads();
    cls_accum(2);

    if (tx < 10) {
        float4 b = ((const float4*)bcls)[tx];
        #pragma unroll
        for (int i = 0; i < 4; i++) {
            int gr = r0 + ty * 4 + i;
            if (gr >= n) continue;
            float4 a = acc[i];
            a.x += b.x; a.y += b.y; a.z += b.z; a.w += b.w;
            *(float4*)(out + (size_t)gr * CC + tx * 4) = a;
        }
    }
}

// ---------------- launch -----------------------------------------------------
extern "C" void kernel_launch(void* const* d_in, const int* in_sizes, int n_in,
                              void* d_out, int out_size)
{
    const float* x      = (const float*)d_in[0];
    const void*  ei     = d_in[1];
    const float* W_ego  = (const float*)d_in[2];
    const float* b_ego  = (const float*)d_in[3];
    const float* W_conv = (const float*)d_in[4];   // [2, 64, 64]
    const float* b_conv = (const float*)d_in[5];   // [2, 64]
    const float* W_cls  = (const float*)d_in[6];   // [192, 40]
    const float* b_cls  = (const float*)d_in[7];   // [40]

    const int N = in_sizes[0] / DH;
    const int E = in_sizes[1] / 2;

    float *y, *h1;
    __half2 *xh, *h1h;
    cudaGetSymbolAddress((void**)&y,   g_y);
    cudaGetSymbolAddress((void**)&h1,  g_h1);
    cudaGetSymbolAddress((void**)&xh,  g_xh);
    cudaGetSymbolAddress((void**)&h1h, g_h1h);

    const int T = 256;
    const int NB = (N + T - 1) / T;
    const int EB = (E + T - 1) / T;
    const dim3 gb(16, 16);
    const int tile_blocks = (N + 63) / 64;
    const int agg_blocks = (int)(((long long)N * 32 + T - 1) / T);
    const int pre_blocks = (int)(((long long)N * 32 + T - 1) / T);

    // CSR build + normalization
    k_init    <<<NB, T>>>(ei, N);
    k_count   <<<EB, T>>>(ei, E);
    k_scan    <<<NB, T>>>(N);
    k_fill    <<<EB, T>>>(ei, E);
    k_prescale<<<pre_blocks, T>>>(x, N);

    // hop 1: y1 = dis*x(self,fp32) + gather(fp16 dis*x);  h1 = relu(dis*(y1@Wc0)+b0)
    k_agg   <<<agg_blocks, T>>>(xh, x, y, N);
    k_gemm_h<<<tile_blocks, gb>>>(y, W_conv, b_conv, h1, N);

    // hop 2: y2 = dis*h1(self,fp32) + gather(fp16 dis*h1)
    k_agg   <<<agg_blocks, T>>>(h1h, h1, y, N);

    // fused classifier
    k_cls<<<tile_blocks, gb>>>(x, h1, y,
                               W_ego, b_ego,
                               W_conv + DH * DH, b_conv + DH,
                               W_cls, b_cls, (float*)d_out, N);
}

// round 11
// speedup vs baseline: 1.0318x; 1.0318x over previous
#include <cuda_runtime.h>
#include <cstdint>

#define MAXN 100000
#define MAXE 1250000
#define DH   64
#define CC   40

// ---------------- device scratch (static; no runtime allocation) -------------
__device__ __align__(16) float g_dis[MAXN];
__device__ int   g_deg[MAXN];
__device__ int   g_rowptr[MAXN + 1];
__device__ int   g_cur[MAXN];
__device__ int   g_csr[MAXE];
__device__ volatile unsigned long long g_pack[512];   // lookback scan state
__device__ int   g_is64;
__device__ __align__(16) float g_y [(size_t)MAXN * DH];
__device__ __align__(16) float g_h1[(size_t)MAXN * DH];

// ---------------- helpers ----------------------------------------------------
__device__ __forceinline__ int edge_at(const void* ei, long long pos) {
    if (g_is64) return (int)((const long long*)ei)[pos];
    return ((const int*)ei)[pos];
}

// zero deg + scan state + int64/int32 detection, one kernel
__global__ void k_init(const void* ei, int n) {
    int i = blockIdx.x * blockDim.x + threadIdx.x;
    if (i < n) g_deg[i] = 0;
    if (i < 512) g_pack[i] = 0ull;
    if (i == 0) {
        const long long* p = (const long long*)ei;
        int ok = 1;
        #pragma unroll
        for (int k = 0; k < 8; k++) {
            long long v = p[k];
            if (v < 0 || v >= (long long)n) ok = 0;
        }
        g_is64 = ok;
    }
}

__global__ void k_count(const void* ei, int E) {
    int e = blockIdx.x * blockDim.x + threadIdx.x;
    if (e < E) atomicAdd(&g_deg[edge_at(ei, (long long)E + e)], 1);
}

// ---- single-pass exclusive scan, WARP-PARALLEL decoupled lookback -----------
#define FLAG_AGG (1ull << 62)
#define FLAG_PRE (2ull << 62)

__global__ void k_scan(int n) {
    __shared__ int s[256];
    __shared__ int s_prefix;
    const int b = blockIdx.x;
    const int t = threadIdx.x;
    const int i = b * 256 + t;
    const int v = (i < n) ? g_deg[i] : 0;

    s[t] = v;
    __syncthreads();
    #pragma unroll
    for (int off = 1; off < 256; off <<= 1) {
        int add = (t >= off) ? s[t - off] : 0;
        __syncthreads();
        s[t] += add;
        __syncthreads();
    }
    // s[t] = inclusive prefix within block; s[255] = block total

    if (t < 32) {                                 // warp 0 does the lookback
        int total = s[255];
        if (b == 0) {
            if (t == 0) {
                g_pack[0] = FLAG_PRE | (unsigned long long)(unsigned)total;
                s_prefix = 0;
            }
        } else {
            if (t == 0)
                g_pack[b] = FLAG_AGG | (unsigned long long)(unsigned)total;
            int prefix = 0;
            int base = b;                          // exclusive upper bound
            while (true) {
                int idx = base - 1 - t;            // t-th nearest predecessor
                unsigned long long p = 0ull;
                if (idx >= 0) {
                    while ((p = g_pack[idx]) == 0ull) { /* spin */ }
                }
                unsigned pre_mask = __ballot_sync(0xffffffffu,
                                                  idx >= 0 && (p & FLAG_PRE));
                if (pre_mask) {
                    int lead = __ffs(pre_mask) - 1;    // nearest PREFIX lane
                    int contrib = (t <= lead) ? (int)(p & 0xFFFFFFFFull) : 0;
                    #pragma unroll
                    for (int o = 16; o; o >>= 1)
                        contrib += __shfl_down_sync(0xffffffffu, contrib, o);
                    prefix += __shfl_sync(0xffffffffu, contrib, 0);
                    break;
                } else {
                    int contrib = (idx >= 0) ? (int)(p & 0xFFFFFFFFull) : 0;
                    #pragma unroll
                    for (int o = 16; o; o >>= 1)
                        contrib += __shfl_down_sync(0xffffffffu, contrib, o);
                    prefix += __shfl_sync(0xffffffffu, contrib, 0);
                    base -= 32;                    // next window (block 0 has PRE)
                }
            }
            if (t == 0) {
                g_pack[b] = FLAG_PRE | (unsigned long long)(unsigned)(prefix + total);
                s_prefix = prefix;
            }
        }
    }
    __syncthreads();

    if (i < n) {
        int excl = s_prefix + s[t] - v;
        g_rowptr[i] = excl;
        g_cur[i]    = excl;
        g_dis[i]    = rsqrtf((float)(v + 1));     // +1 = self-loop
        if (i == n - 1) g_rowptr[n] = excl + v;
    }
}

__global__ void k_fill(const void* ei, int E) {
    int e = blockIdx.x * blockDim.x + threadIdx.x;
    if (e < E) {
        int r = edge_at(ei, (long long)e);
        int c = edge_at(ei, (long long)E + e);
        int pos = atomicAdd(&g_cur[c], 1);
        g_csr[pos] = r;
    }
}

// -------- gather-first aggregation: y_i = dis_i*src_i + sum_nbr dis_r*src_r ---
// warp per node (no divergence), lane owns float2. (R6 exact — best measured.)
__global__ void k_agg(const float* __restrict__ src, float* __restrict__ y, int n)
{
    int w = (blockIdx.x * blockDim.x + threadIdx.x) >> 5;
    int lane = threadIdx.x & 31;
    if (w >= n) return;

    const float2* H = (const float2*)src;
    float  dw = g_dis[w];
    float2 v0 = H[(size_t)w * 32 + lane];
    float2 acc;
    acc.x = dw * v0.x;
    acc.y = dw * v0.y;

    int p   = g_rowptr[w];
    int end = g_rowptr[w + 1];
    for (; p + 3 < end; p += 4) {
        int s0 = __ldg(&g_csr[p]);
        int s1 = __ldg(&g_csr[p + 1]);
        int s2 = __ldg(&g_csr[p + 2]);
        int s3 = __ldg(&g_csr[p + 3]);
        float d0 = __ldg(&g_dis[s0]);
        float d1 = __ldg(&g_dis[s1]);
        float d2 = __ldg(&g_dis[s2]);
        float d3 = __ldg(&g_dis[s3]);
        float2 a = H[(size_t)s0 * 32 + lane];
        float2 b = H[(size_t)s1 * 32 + lane];
        float2 c = H[(size_t)s2 * 32 + lane];
        float2 d = H[(size_t)s3 * 32 + lane];
        acc.x = fmaf(d0, a.x, fmaf(d1, b.x, fmaf(d2, c.x, fmaf(d3, d.x, acc.x))));
        acc.y = fmaf(d0, a.y, fmaf(d1, b.y, fmaf(d2, c.y, fmaf(d3, d.y, acc.y))));
    }
    for (; p < end; p++) {
        int s0 = __ldg(&g_csr[p]);
        float d0 = __ldg(&g_dis[s0]);
        float2 a = H[(size_t)s0 * 32 + lane];
        acc.x = fmaf(d0, a.x, acc.x);
        acc.y = fmaf(d0, a.y, acc.y);
    }
    ((float2*)y)[(size_t)w * 32 + lane] = acc;
}

// ------------- GEMM+finish: h = relu(dis_i * (y @ W) + b) --------------------
__global__ void k_gemm_h(const float* __restrict__ Y, const float* __restrict__ W,
                         const float* __restrict__ bias, float* __restrict__ out, int n)
{
    __shared__ float  Xs[64 * 64];
    __shared__ float4 Ws[64 * 16];

    const int tx = threadIdx.x, ty = threadIdx.y;
    const int tid = ty * 16 + tx;

    const float4* Wv = (const float4*)W;
    #pragma unroll
    for (int i = 0; i < 4; i++) Ws[tid + i * 256] = Wv[tid + i * 256];

    const int r0 = blockIdx.x * 64;
    #pragma unroll
    for (int i = 0; i < 4; i++) {
        int idx = tid + i * 256;
        int rr = idx >> 4, cc = idx & 15;
        int gr = r0 + rr;
        float4 v = make_float4(0.f, 0.f, 0.f, 0.f);
        if (gr < n) v = ((const float4*)(Y + (size_t)gr * DH))[cc];
        *(float4*)&Xs[rr * 64 + cc * 4] = v;
    }
    __syncthreads();

    float4 acc[4];
    #pragma unroll
    for (int i = 0; i < 4; i++) acc[i] = make_float4(0.f, 0.f, 0.f, 0.f);

    #pragma unroll
    for (int k4 = 0; k4 < 16; k4++) {
        float4 xv[4];
        #pragma unroll
        for (int i = 0; i < 4; i++)
            xv[i] = *(const float4*)&Xs[(ty * 4 + i) * 64 + k4 * 4];
        #pragma unroll
        for (int j = 0; j < 4; j++) {
            float4 w = Ws[(k4 * 4 + j) * 16 + tx];
            #pragma unroll
            for (int i = 0; i < 4; i++) {
                float xs = (j == 0) ? xv[i].x : (j == 1) ? xv[i].y : (j == 2) ? xv[i].z : xv[i].w;
                acc[i].x = fmaf(xs, w.x, acc[i].x);
                acc[i].y = fmaf(xs, w.y, acc[i].y);
                acc[i].z = fmaf(xs, w.z, acc[i].z);
                acc[i].w = fmaf(xs, w.w, acc[i].w);
            }
        }
    }

    float4 b = ((const float4*)bias)[tx];
    #pragma unroll
    for (int i = 0; i < 4; i++) {
        int gr = r0 + ty * 4 + i;
        if (gr >= n) continue;
        float s = g_dis[gr];
        float4 a = acc[i];
        a.x = fmaxf(fmaf(s, a.x, b.x), 0.f);
        a.y = fmaxf(fmaf(s, a.y, b.y), 0.f);
        a.z = fmaxf(fmaf(s, a.z, b.z), 0.f);
        a.w = fmaxf(fmaf(s, a.w, b.w), 0.f);
        ((float4*)(out + (size_t)gr * DH))[tx] = a;
    }
}

// ---------------- fused classifier -------------------------------------------
// out = [ego | h1 | h2] @ W_cls + b_cls
//   ego = relu(x @ W_ego + b_ego)       (in-register from x tile)
//   h2  = relu(dis*(y2 @ Wc1) + b1)     (in-register from pre-aggregated y2)
__global__ void k_cls(const float* __restrict__ x, const float* __restrict__ h1,
                      const float* __restrict__ y2,
                      const float* __restrict__ Wego, const float* __restrict__ bego,
                      const float* __restrict__ Wc1,  const float* __restrict__ bc1,
                      const float* __restrict__ Wcls, const float* __restrict__ bcls,
                      float* __restrict__ out, int n)
{
    __shared__ float  Xs[64 * 68];     // 17408 B
    __shared__ float4 Wcs[192 * 10];   // 30720 B

    const int tx = threadIdx.x, ty = threadIdx.y;
    const int tid = ty * 16 + tx;
    const int r0 = blockIdx.x * 64;

    const float4* Wclsv = (const float4*)Wcls;
    #pragma unroll
    for (int i = tid; i < 1920; i += 256) Wcs[i] = Wclsv[i];

    float4 acc[4];
    #pragma unroll
    for (int i = 0; i < 4; i++) acc[i] = make_float4(0.f, 0.f, 0.f, 0.f);

    auto load_tile = [&](const float* S) {
        #pragma unroll
        for (int i = 0; i < 4; i++) {
            int idx = tid + i * 256;
            int rr = idx >> 4, cc = idx & 15;
            int gr = r0 + rr;
            float4 v = make_float4(0.f, 0.f, 0.f, 0.f);
            if (gr < n) v = ((const float4*)(S + (size_t)gr * DH))[cc];
            *(float4*)&Xs[rr * 68 + cc * 4] = v;
        }
    };

    // in-place 64x64 transform of Xs: Xs = relu(scale*(Xs@W)+b)
    auto transform = [&](const float* W, const float* bias, bool use_dis) {
        const float4* Wv = (const float4*)W;
        float4 t[4];
        #pragma unroll
        for (int i = 0; i < 4; i++) t[i] = make_float4(0.f, 0.f, 0.f, 0.f);
        #pragma unroll
        for (int k4 = 0; k4 < 16; k4++) {
            float4 xv[4];
            #pragma unroll
            for (int i = 0; i < 4; i++)
                xv[i] = *(const float4*)&Xs[(ty * 4 + i) * 68 + k4 * 4];
            #pragma unroll
            for (int j = 0; j < 4; j++) {
                float4 w = __ldg(&Wv[(k4 * 4 + j) * 16 + tx]);
                #pragma unroll
                for (int i = 0; i < 4; i++) {
                    float xs = (j == 0) ? xv[i].x : (j == 1) ? xv[i].y : (j == 2) ? xv[i].z : xv[i].w;
                    t[i].x = fmaf(xs, w.x, t[i].x);
                    t[i].y = fmaf(xs, w.y, t[i].y);
                    t[i].z = fmaf(xs, w.z, t[i].z);
                    t[i].w = fmaf(xs, w.w, t[i].w);
                }
            }
        }
        float4 b = __ldg(&((const float4*)bias)[tx]);
        __syncthreads();               // done reading old Xs
        #pragma unroll
        for (int i = 0; i < 4; i++) {
            int gr = r0 + ty * 4 + i;
            float s = 1.0f;
            if (use_dis) s = (gr < n) ? g_dis[gr] : 0.f;
            float4 a = t[i];
            a.x = fmaxf(fmaf(s, a.x, b.x), 0.f);
            a.y = fmaxf(fmaf(s, a.y, b.y), 0.f);
            a.z = fmaxf(fmaf(s, a.z, b.z), 0.f);
            a.w = fmaxf(fmaf(s, a.w, b.w), 0.f);
            *(float4*)&Xs[(ty * 4 + i) * 68 + tx * 4] = a;
        }
    };

    auto cls_accum = [&](int c) {
        if (tx < 10) {
            #pragma unroll
            for (int k4 = 0; k4 < 16; k4++) {
                float4 xv[4];
                #pragma unroll
                for (int i = 0; i < 4; i++)
                    xv[i] = *(const float4*)&Xs[(ty * 4 + i) * 68 + k4 * 4];
                #pragma unroll
                for (int j = 0; j < 4; j++) {
                    float4 w = Wcs[(c * 64 + k4 * 4 + j) * 10 + tx];
                    #pragma unroll
                    for (int i = 0; i < 4; i++) {
                        float xs = (j == 0) ? xv[i].x : (j == 1) ? xv[i].y : (j == 2) ? xv[i].z : xv[i].w;
                        acc[i].x = fmaf(xs, w.x, acc[i].x);
                        acc[i].y = fmaf(xs, w.y, acc[i].y);
                        acc[i].z = fmaf(xs, w.z, acc[i].z);
                        acc[i].w = fmaf(xs, w.w, acc[i].w);
                    }
                }
            }
        }
    };

    // phase 0: ego = relu(x @ Wego + bego)
    load_tile(x);
    __syncthreads();
    transform(Wego, bego, false);
    __syncthreads();
    cls_accum(0);
    __syncthreads();

    // phase 1: h1 (materialized)
    load_tile(h1);
    __syncthreads();
    cls_accum(1);
    __syncthreads();

    // phase 2: h2 = relu(dis*(y2 @ Wc1) + b1)
    load_tile(y2);
    __syncthreads();
    transform(Wc1, bc1, true);
    __syncthreads();
    cls_accum(2);

    if (tx < 10) {
        float4 b = ((const float4*)bcls)[tx];
        #pragma unroll
        for (int i = 0; i < 4; i++) {
            int gr = r0 + ty * 4 + i;
            if (gr >= n) continue;
            float4 a = acc[i];
            a.x += b.x; a.y += b.y; a.z += b.z; a.w += b.w;
            *(float4*)(out + (size_t)gr * CC + tx * 4) = a;
        }
    }
}

// ---------------- launch -----------------------------------------------------
extern "C" void kernel_launch(void* const* d_in, const int* in_sizes, int n_in,
                              void* d_out, int out_size)
{
    const float* x      = (const float*)d_in[0];
    const void*  ei     = d_in[1];
    const float* W_ego  = (const float*)d_in[2];
    const float* b_ego  = (const float*)d_in[3];
    const float* W_conv = (const float*)d_in[4];   // [2, 64, 64]
    const float* b_conv = (const float*)d_in[5];   // [2, 64]
    const float* W_cls  = (const float*)d_in[6];   // [192, 40]
    const float* b_cls  = (const float*)d_in[7];   // [40]

    const int N = in_sizes[0] / DH;
    const int E = in_sizes[1] / 2;

    float *y, *h1;
    cudaGetSymbolAddress((void**)&y,  g_y);
    cudaGetSymbolAddress((void**)&h1, g_h1);

    const int T = 256;
    const int NB = (N + T - 1) / T;
    const int EB = (E + T - 1) / T;
    const dim3 gb(16, 16);
    const int tile_blocks = (N + 63) / 64;
    const int agg_blocks = (int)(((long long)N * 32 + T - 1) / T);

    // CSR build + normalization
    k_init <<<NB, T>>>(ei, N);
    k_count<<<EB, T>>>(ei, E);
    k_scan <<<NB, T>>>(N);
    k_fill <<<EB, T>>>(ei, E);

    // hop 1: y1 = gather(dis*x);  h1 = relu(dis*(y1@Wc0) + b0)
    k_agg   <<<agg_blocks, T>>>(x, y, N);
    k_gemm_h<<<tile_blocks, gb>>>(y, W_conv, b_conv, h1, N);

    // hop 2: y2 = gather(dis*h1)   (h2 virtualized into k_cls)
    k_agg   <<<agg_blocks, T>>>(h1, y, N);

    // fused classifier
    k_cls<<<tile_blocks, gb>>>(x, h1, y,
                               W_ego, b_ego,
                               W_conv + DH * DH, b_conv + DH,
                               W_cls, b_cls, (float*)d_out, N);
}

// round 12
// speedup vs baseline: 1.0663x; 1.0335x over previous
#include <cuda_runtime.h>
#include <cstdint>

#define MAXN 100000
#define MAXE 1250000
#define DH   64
#define CC   40

typedef unsigned long long u64;

// ---- packed f32x2 helpers (sm_10x; PTX-only, ptxas won't auto-fuse) ---------
__device__ __forceinline__ u64 pk2(float lo, float hi) {
    u64 r;
    asm("mov.b64 %0, {%1, %2};" : "=l"(r) : "f"(lo), "f"(hi));
    return r;
}
__device__ __forceinline__ void fma2(u64& d, u64 a, u64 b) {
    asm("fma.rn.f32x2 %0, %1, %2, %0;" : "+l"(d) : "l"(a), "l"(b));
}
__device__ __forceinline__ void unpk2(u64 v, float& lo, float& hi) {
    asm("mov.b64 {%0, %1}, %2;" : "=f"(lo), "=f"(hi) : "l"(v));
}

// ---------------- device scratch (static; no runtime allocation) -------------
__device__ __align__(16) float g_dis[MAXN];
__device__ int   g_deg[MAXN];
__device__ int   g_rowptr[MAXN + 1];
__device__ int   g_cur[MAXN];
__device__ int   g_csr[MAXE];
__device__ volatile u64 g_pack[512];
__device__ int   g_is64;
__device__ __align__(16) float g_y [(size_t)MAXN * DH];
__device__ __align__(16) float g_h1[(size_t)MAXN * DH];

// ---------------- helpers ----------------------------------------------------
__device__ __forceinline__ int edge_at(const void* ei, long long pos) {
    if (g_is64) return (int)((const long long*)ei)[pos];
    return ((const int*)ei)[pos];
}

__global__ void k_init(const void* ei, int n) {
    int i = blockIdx.x * blockDim.x + threadIdx.x;
    if (i < n) g_deg[i] = 0;
    if (i < 512) g_pack[i] = 0ull;
    if (i == 0) {
        const long long* p = (const long long*)ei;
        int ok = 1;
        #pragma unroll
        for (int k = 0; k < 8; k++) {
            long long v = p[k];
            if (v < 0 || v >= (long long)n) ok = 0;
        }
        g_is64 = ok;
    }
}

__global__ void k_count(const void* ei, int E) {
    int e = blockIdx.x * blockDim.x + threadIdx.x;
    if (e < E) atomicAdd(&g_deg[edge_at(ei, (long long)E + e)], 1);
}

// ---- single-pass exclusive scan, warp-parallel decoupled lookback -----------
#define FLAG_AGG (1ull << 62)
#define FLAG_PRE (2ull << 62)

__global__ void k_scan(int n) {
    __shared__ int s[256];
    __shared__ int s_prefix;
    const int b = blockIdx.x;
    const int t = threadIdx.x;
    const int i = b * 256 + t;
    const int v = (i < n) ? g_deg[i] : 0;

    s[t] = v;
    __syncthreads();
    #pragma unroll
    for (int off = 1; off < 256; off <<= 1) {
        int add = (t >= off) ? s[t - off] : 0;
        __syncthreads();
        s[t] += add;
        __syncthreads();
    }

    if (t < 32) {
        int total = s[255];
        if (b == 0) {
            if (t == 0) {
                g_pack[0] = FLAG_PRE | (u64)(unsigned)total;
                s_prefix = 0;
            }
        } else {
            if (t == 0)
                g_pack[b] = FLAG_AGG | (u64)(unsigned)total;
            int prefix = 0;
            int base = b;
            while (true) {
                int idx = base - 1 - t;
                u64 p = 0ull;
                if (idx >= 0) {
                    while ((p = g_pack[idx]) == 0ull) { }
                }
                unsigned pre_mask = __ballot_sync(0xffffffffu,
                                                  idx >= 0 && (p & FLAG_PRE));
                if (pre_mask) {
                    int lead = __ffs(pre_mask) - 1;
                    int contrib = (t <= lead) ? (int)(p & 0xFFFFFFFFull) : 0;
                    #pragma unroll
                    for (int o = 16; o; o >>= 1)
                        contrib += __shfl_down_sync(0xffffffffu, contrib, o);
                    prefix += __shfl_sync(0xffffffffu, contrib, 0);
                    break;
                } else {
                    int contrib = (idx >= 0) ? (int)(p & 0xFFFFFFFFull) : 0;
                    #pragma unroll
                    for (int o = 16; o; o >>= 1)
                        contrib += __shfl_down_sync(0xffffffffu, contrib, o);
                    prefix += __shfl_sync(0xffffffffu, contrib, 0);
                    base -= 32;
                }
            }
            if (t == 0) {
                g_pack[b] = FLAG_PRE | (u64)(unsigned)(prefix + total);
                s_prefix = prefix;
            }
        }
    }
    __syncthreads();

    if (i < n) {
        int excl = s_prefix + s[t] - v;
        g_rowptr[i] = excl;
        g_cur[i]    = excl;
        g_dis[i]    = rsqrtf((float)(v + 1));
        if (i == n - 1) g_rowptr[n] = excl + v;
    }
}

__global__ void k_fill(const void* ei, int E) {
    int e = blockIdx.x * blockDim.x + threadIdx.x;
    if (e < E) {
        int r = edge_at(ei, (long long)e);
        int c = edge_at(ei, (long long)E + e);
        int pos = atomicAdd(&g_cur[c], 1);
        g_csr[pos] = r;
    }
}

// -------- gather-first aggregation (R6 exact — best measured) ----------------
__global__ void k_agg(const float* __restrict__ src, float* __restrict__ y, int n)
{
    int w = (blockIdx.x * blockDim.x + threadIdx.x) >> 5;
    int lane = threadIdx.x & 31;
    if (w >= n) return;

    const float2* H = (const float2*)src;
    float  dw = g_dis[w];
    float2 v0 = H[(size_t)w * 32 + lane];
    float2 acc;
    acc.x = dw * v0.x;
    acc.y = dw * v0.y;

    int p   = g_rowptr[w];
    int end = g_rowptr[w + 1];
    for (; p + 3 < end; p += 4) {
        int s0 = __ldg(&g_csr[p]);
        int s1 = __ldg(&g_csr[p + 1]);
        int s2 = __ldg(&g_csr[p + 2]);
        int s3 = __ldg(&g_csr[p + 3]);
        float d0 = __ldg(&g_dis[s0]);
        float d1 = __ldg(&g_dis[s1]);
        float d2 = __ldg(&g_dis[s2]);
        float d3 = __ldg(&g_dis[s3]);
        float2 a = H[(size_t)s0 * 32 + lane];
        float2 b = H[(size_t)s1 * 32 + lane];
        float2 c = H[(size_t)s2 * 32 + lane];
        float2 d = H[(size_t)s3 * 32 + lane];
        acc.x = fmaf(d0, a.x, fmaf(d1, b.x, fmaf(d2, c.x, fmaf(d3, d.x, acc.x))));
        acc.y = fmaf(d0, a.y, fmaf(d1, b.y, fmaf(d2, c.y, fmaf(d3, d.y, acc.y))));
    }
    for (; p < end; p++) {
        int s0 = __ldg(&g_csr[p]);
        float d0 = __ldg(&g_dis[s0]);
        float2 a = H[(size_t)s0 * 32 + lane];
        acc.x = fmaf(d0, a.x, acc.x);
        acc.y = fmaf(d0, a.y, acc.y);
    }
    ((float2*)y)[(size_t)w * 32 + lane] = acc;
}

// ------------- GEMM+finish: h = relu(dis_i * (y @ W) + b), f32x2 core --------
__global__ void k_gemm_h(const float* __restrict__ Y, const float* __restrict__ W,
                         const float* __restrict__ bias, float* __restrict__ out, int n)
{
    __shared__ float  Xs[64 * 64];
    __shared__ float4 Ws[64 * 16];

    const int tx = threadIdx.x, ty = threadIdx.y;
    const int tid = ty * 16 + tx;

    const float4* Wv = (const float4*)W;
    #pragma unroll
    for (int i = 0; i < 4; i++) Ws[tid + i * 256] = Wv[tid + i * 256];

    const int r0 = blockIdx.x * 64;
    #pragma unroll
    for (int i = 0; i < 4; i++) {
        int idx = tid + i * 256;
        int rr = idx >> 4, cc = idx & 15;
        int gr = r0 + rr;
        float4 v = make_float4(0.f, 0.f, 0.f, 0.f);
        if (gr < n) v = ((const float4*)(Y + (size_t)gr * DH))[cc];
        *(float4*)&Xs[rr * 64 + cc * 4] = v;
    }
    __syncthreads();

    u64 a01[4], a23[4];
    #pragma unroll
    for (int i = 0; i < 4; i++) { a01[i] = 0ull; a23[i] = 0ull; }

    #pragma unroll
    for (int k4 = 0; k4 < 16; k4++) {
        float4 xv[4];
        #pragma unroll
        for (int i = 0; i < 4; i++)
            xv[i] = *(const float4*)&Xs[(ty * 4 + i) * 64 + k4 * 4];
        #pragma unroll
        for (int j = 0; j < 4; j++) {
            float4 w = Ws[(k4 * 4 + j) * 16 + tx];
            u64 w01 = pk2(w.x, w.y);
            u64 w23 = pk2(w.z, w.w);
            #pragma unroll
            for (int i = 0; i < 4; i++) {
                float xs = (j == 0) ? xv[i].x : (j == 1) ? xv[i].y : (j == 2) ? xv[i].z : xv[i].w;
                u64 xd = pk2(xs, xs);
                fma2(a01[i], xd, w01);
                fma2(a23[i], xd, w23);
            }
        }
    }

    float4 b = ((const float4*)bias)[tx];
    #pragma unroll
    for (int i = 0; i < 4; i++) {
        int gr = r0 + ty * 4 + i;
        if (gr >= n) continue;
        float s = g_dis[gr];
        float4 a;
        unpk2(a01[i], a.x, a.y);
        unpk2(a23[i], a.z, a.w);
        a.x = fmaxf(fmaf(s, a.x, b.x), 0.f);
        a.y = fmaxf(fmaf(s, a.y, b.y), 0.f);
        a.z = fmaxf(fmaf(s, a.z, b.z), 0.f);
        a.w = fmaxf(fmaf(s, a.w, b.w), 0.f);
        ((float4*)(out + (size_t)gr * DH))[tx] = a;
    }
}

// ---------------- fused classifier, f32x2 core --------------------------------
__global__ void k_cls(const float* __restrict__ x, const float* __restrict__ h1,
                      const float* __restrict__ y2,
                      const float* __restrict__ Wego, const float* __restrict__ bego,
                      const float* __restrict__ Wc1,  const float* __restrict__ bc1,
                      const float* __restrict__ Wcls, const float* __restrict__ bcls,
                      float* __restrict__ out, int n)
{
    __shared__ float  Xs[64 * 68];     // 17408 B
    __shared__ float4 Wcs[192 * 10];   // 30720 B

    const int tx = threadIdx.x, ty = threadIdx.y;
    const int tid = ty * 16 + tx;
    const int r0 = blockIdx.x * 64;

    const float4* Wclsv = (const float4*)Wcls;
    #pragma unroll
    for (int i = tid; i < 1920; i += 256) Wcs[i] = Wclsv[i];

    u64 c01[4], c23[4];                // classifier accumulators (tx<10 lanes)
    #pragma unroll
    for (int i = 0; i < 4; i++) { c01[i] = 0ull; c23[i] = 0ull; }

    auto load_tile = [&](const float* S) {
        #pragma unroll
        for (int i = 0; i < 4; i++) {
            int idx = tid + i * 256;
            int rr = idx >> 4, cc = idx & 15;
            int gr = r0 + rr;
            float4 v = make_float4(0.f, 0.f, 0.f, 0.f);
            if (gr < n) v = ((const float4*)(S + (size_t)gr * DH))[cc];
            *(float4*)&Xs[rr * 68 + cc * 4] = v;
        }
    };

    // in-place 64x64 transform of Xs: Xs = relu(scale*(Xs@W)+b), f32x2 core
    auto transform = [&](const float* W, const float* bias, bool use_dis) {
        const float4* Wv = (const float4*)W;
        u64 t01[4], t23[4];
        #pragma unroll
        for (int i = 0; i < 4; i++) { t01[i] = 0ull; t23[i] = 0ull; }
        #pragma unroll
        for (int k4 = 0; k4 < 16; k4++) {
            float4 xv[4];
            #pragma unroll
            for (int i = 0; i < 4; i++)
                xv[i] = *(const float4*)&Xs[(ty * 4 + i) * 68 + k4 * 4];
            #pragma unroll
            for (int j = 0; j < 4; j++) {
                float4 w = __ldg(&Wv[(k4 * 4 + j) * 16 + tx]);
                u64 w01 = pk2(w.x, w.y);
                u64 w23 = pk2(w.z, w.w);
                #pragma unroll
                for (int i = 0; i < 4; i++) {
                    float xs = (j == 0) ? xv[i].x : (j == 1) ? xv[i].y : (j == 2) ? xv[i].z : xv[i].w;
                    u64 xd = pk2(xs, xs);
                    fma2(t01[i], xd, w01);
                    fma2(t23[i], xd, w23);
                }
            }
        }
        float4 b = __ldg(&((const float4*)bias)[tx]);
        __syncthreads();               // done reading old Xs
        #pragma unroll
        for (int i = 0; i < 4; i++) {
            int gr = r0 + ty * 4 + i;
            float s = 1.0f;
            if (use_dis) s = (gr < n) ? g_dis[gr] : 0.f;
            float4 a;
            unpk2(t01[i], a.x, a.y);
            unpk2(t23[i], a.z, a.w);
            a.x = fmaxf(fmaf(s, a.x, b.x), 0.f);
            a.y = fmaxf(fmaf(s, a.y, b.y), 0.f);
            a.z = fmaxf(fmaf(s, a.z, b.z), 0.f);
            a.w = fmaxf(fmaf(s, a.w, b.w), 0.f);
            *(float4*)&Xs[(ty * 4 + i) * 68 + tx * 4] = a;
        }
    };

    auto cls_accum = [&](int c) {
        if (tx < 10) {
            #pragma unroll
            for (int k4 = 0; k4 < 16; k4++) {
                float4 xv[4];
                #pragma unroll
                for (int i = 0; i < 4; i++)
                    xv[i] = *(const float4*)&Xs[(ty * 4 + i) * 68 + k4 * 4];
                #pragma unroll
                for (int j = 0; j < 4; j++) {
                    float4 w = Wcs[(c * 64 + k4 * 4 + j) * 10 + tx];
                    u64 w01 = pk2(w.x, w.y);
                    u64 w23 = pk2(w.z, w.w);
                    #pragma unroll
                    for (int i = 0; i < 4; i++) {
                        float xs = (j == 0) ? xv[i].x : (j == 1) ? xv[i].y : (j == 2) ? xv[i].z : xv[i].w;
                        u64 xd = pk2(xs, xs);
                        fma2(c01[i], xd, w01);
                        fma2(c23[i], xd, w23);
                    }
                }
            }
        }
    };

    // phase 0: ego = relu(x @ Wego + bego)
    load_tile(x);
    __syncthreads();
    transform(Wego, bego, false);
    __syncthreads();
    cls_accum(0);
    __syncthreads();

    // phase 1: h1 (materialized)
    load_tile(h1);
    __syncthreads();
    cls_accum(1);
    __syncthreads();

    // phase 2: h2 = relu(dis*(y2 @ Wc1) + b1)
    load_tile(y2);
    __syncthreads();
    transform(Wc1, bc1, true);
    __syncthreads();
    cls_accum(2);

    if (tx < 10) {
        float4 b = ((const float4*)bcls)[tx];
        #pragma unroll
        for (int i = 0; i < 4; i++) {
            int gr = r0 + ty * 4 + i;
            if (gr >= n) continue;
            float4 a;
            unpk2(c01[i], a.x, a.y);
            unpk2(c23[i], a.z, a.w);
            a.x += b.x; a.y += b.y; a.z += b.z; a.w += b.w;
            *(float4*)(out + (size_t)gr * CC + tx * 4) = a;
        }
    }
}

// ---------------- launch -----------------------------------------------------
extern "C" void kernel_launch(void* const* d_in, const int* in_sizes, int n_in,
                              void* d_out, int out_size)
{
    const float* x      = (const float*)d_in[0];
    const void*  ei     = d_in[1];
    const float* W_ego  = (const float*)d_in[2];
    const float* b_ego  = (const float*)d_in[3];
    const float* W_conv = (const float*)d_in[4];   // [2, 64, 64]
    const float* b_conv = (const float*)d_in[5];   // [2, 64]
    const float* W_cls  = (const float*)d_in[6];   // [192, 40]
    const float* b_cls  = (const float*)d_in[7];   // [40]

    const int N = in_sizes[0] / DH;
    const int E = in_sizes[1] / 2;

    float *y, *h1;
    cudaGetSymbolAddress((void**)&y,  g_y);
    cudaGetSymbolAddress((void**)&h1, g_h1);

    const int T = 256;
    const int NB = (N + T - 1) / T;
    const int EB = (E + T - 1) / T;
    const dim3 gb(16, 16);
    const int tile_blocks = (N + 63) / 64;
    const int agg_blocks = (int)(((long long)N * 32 + T - 1) / T);

    // CSR build + normalization
    k_init <<<NB, T>>>(ei, N);
    k_count<<<EB, T>>>(ei, E);
    k_scan <<<NB, T>>>(N);
    k_fill <<<EB, T>>>(ei, E);

    // hop 1
    k_agg   <<<agg_blocks, T>>>(x, y, N);
    k_gemm_h<<<tile_blocks, gb>>>(y, W_conv, b_conv, h1, N);

    // hop 2
    k_agg   <<<agg_blocks, T>>>(h1, y, N);

    // fused classifier
    k_cls<<<tile_blocks, gb>>>(x, h1, y,
                               W_ego, b_ego,
                               W_conv + DH * DH, b_conv + DH,
                               W_cls, b_cls, (float*)d_out, N);
}

// round 13
// speedup vs baseline: 1.0842x; 1.0168x over previous
#include <cuda_runtime.h>
#include <cstdint>

#define MAXN 100000
#define MAXE 1250000
#define DH   64
#define CC   40
#define ELLW 40          // ELL width; Poisson(12.5) => P(deg>40) ~ 1e-10
#define OVFCAP 8192

typedef unsigned long long u64;

// ---- packed f32x2 helpers (sm_10x; PTX-only, ptxas won't auto-fuse) ---------
__device__ __forceinline__ u64 pk2(float lo, float hi) {
    u64 r;
    asm("mov.b64 %0, {%1, %2};" : "=l"(r) : "f"(lo), "f"(hi));
    return r;
}
__device__ __forceinline__ void fma2(u64& d, u64 a, u64 b) {
    asm("fma.rn.f32x2 %0, %1, %2, %0;" : "+l"(d) : "l"(a), "l"(b));
}
__device__ __forceinline__ void unpk2(u64 v, float& lo, float& hi) {
    asm("mov.b64 {%0, %1}, %2;" : "=f"(lo), "=f"(hi) : "l"(v));
}

// ---------------- device scratch (static; no runtime allocation) -------------
__device__ __align__(16) float g_dis[MAXN];
__device__ int   g_deg[MAXN];
__device__ int   g_ell[(size_t)MAXN * ELLW];
__device__ int2  g_ovf[OVFCAP];
__device__ int   g_ovfn;
__device__ int   g_is64;
__device__ __align__(16) float g_y [(size_t)MAXN * DH];
__device__ __align__(16) float g_h1[(size_t)MAXN * DH];

// ---------------- helpers ----------------------------------------------------
__device__ __forceinline__ int edge_at(const void* ei, long long pos) {
    if (g_is64) return (int)((const long long*)ei)[pos];
    return ((const int*)ei)[pos];
}

// zero deg + overflow counter + int64/int32 detection
__global__ void k_init(const void* ei, int n) {
    int i = blockIdx.x * blockDim.x + threadIdx.x;
    if (i < n) g_deg[i] = 0;
    if (i == 0) {
        g_ovfn = 0;
        const long long* p = (const long long*)ei;
        int ok = 1;
        #pragma unroll
        for (int k = 0; k < 8; k++) {
            long long v = p[k];
            if (v < 0 || v >= (long long)n) ok = 0;
        }
        g_is64 = ok;
    }
}

// single edge pass: deg count + ELL fill (+ overflow capture)
__global__ void k_fill(const void* ei, int E) {
    int e = blockIdx.x * blockDim.x + threadIdx.x;
    if (e < E) {
        int r = edge_at(ei, (long long)e);
        int c = edge_at(ei, (long long)E + e);
        int pos = atomicAdd(&g_deg[c], 1);
        if (pos < ELLW) {
            g_ell[(size_t)c * ELLW + pos] = r;
        } else {
            int k = atomicAdd(&g_ovfn, 1);
            if (k < OVFCAP) g_ovf[k] = make_int2(r, c);
        }
    }
}

__global__ void k_dis(int n) {
    int i = blockIdx.x * blockDim.x + threadIdx.x;
    if (i < n) g_dis[i] = rsqrtf((float)(g_deg[i] + 1));   // +1 = self-loop
}

// -------- gather-first aggregation: y_i = dis_i*src_i + sum_nbr dis_r*src_r ---
// warp per node, lane owns float2; ELL fixed-stride rows (broadcast loads).
__global__ void k_agg(const float* __restrict__ src, float* __restrict__ y, int n)
{
    int w = (blockIdx.x * blockDim.x + threadIdx.x) >> 5;
    int lane = threadIdx.x & 31;
    if (w >= n) return;

    const float2* H = (const float2*)src;
    float  dw = g_dis[w];
    float2 v0 = H[(size_t)w * 32 + lane];
    float2 acc;
    acc.x = dw * v0.x;
    acc.y = dw * v0.y;

    const int deg = g_deg[w];
    const int end = deg < ELLW ? deg : ELLW;
    const int* row = &g_ell[(size_t)w * ELLW];

    int p = 0;
    for (; p + 3 < end; p += 4) {
        int s0 = __ldg(&row[p]);
        int s1 = __ldg(&row[p + 1]);
        int s2 = __ldg(&row[p + 2]);
        int s3 = __ldg(&row[p + 3]);
        float d0 = __ldg(&g_dis[s0]);
        float d1 = __ldg(&g_dis[s1]);
        float d2 = __ldg(&g_dis[s2]);
        float d3 = __ldg(&g_dis[s3]);
        float2 a = H[(size_t)s0 * 32 + lane];
        float2 b = H[(size_t)s1 * 32 + lane];
        float2 c = H[(size_t)s2 * 32 + lane];
        float2 d = H[(size_t)s3 * 32 + lane];
        acc.x = fmaf(d0, a.x, fmaf(d1, b.x, fmaf(d2, c.x, fmaf(d3, d.x, acc.x))));
        acc.y = fmaf(d0, a.y, fmaf(d1, b.y, fmaf(d2, c.y, fmaf(d3, d.y, acc.y))));
    }
    for (; p < end; p++) {
        int s0 = __ldg(&row[p]);
        float d0 = __ldg(&g_dis[s0]);
        float2 a = H[(size_t)s0 * 32 + lane];
        acc.x = fmaf(d0, a.x, acc.x);
        acc.y = fmaf(d0, a.y, acc.y);
    }

    // overflow edges (normally none): only overflowing targets scan the buffer
    if (deg > ELLW) {
        int novf = g_ovfn;
        for (int i = 0; i < novf; i++) {
            int2 rc = g_ovf[i];
            if (rc.y == w) {
                float d0 = g_dis[rc.x];
                float2 a = H[(size_t)rc.x * 32 + lane];
                acc.x = fmaf(d0, a.x, acc.x);
                acc.y = fmaf(d0, a.y, acc.y);
            }
        }
    }

    ((float2*)y)[(size_t)w * 32 + lane] = acc;
}

// ------------- GEMM+finish: h = relu(dis_i * (y @ W) + b), f32x2 core --------
__global__ void k_gemm_h(const float* __restrict__ Y, const float* __restrict__ W,
                         const float* __restrict__ bias, float* __restrict__ out, int n)
{
    __shared__ float  Xs[64 * 64];
    __shared__ float4 Ws[64 * 16];

    const int tx = threadIdx.x, ty = threadIdx.y;
    const int tid = ty * 16 + tx;

    const float4* Wv = (const float4*)W;
    #pragma unroll
    for (int i = 0; i < 4; i++) Ws[tid + i * 256] = Wv[tid + i * 256];

    const int r0 = blockIdx.x * 64;
    #pragma unroll
    for (int i = 0; i < 4; i++) {
        int idx = tid + i * 256;
        int rr = idx >> 4, cc = idx & 15;
        int gr = r0 + rr;
        float4 v = make_float4(0.f, 0.f, 0.f, 0.f);
        if (gr < n) v = ((const float4*)(Y + (size_t)gr * DH))[cc];
        *(float4*)&Xs[rr * 64 + cc * 4] = v;
    }
    __syncthreads();

    u64 a01[4], a23[4];
    #pragma unroll
    for (int i = 0; i < 4; i++) { a01[i] = 0ull; a23[i] = 0ull; }

    #pragma unroll
    for (int k4 = 0; k4 < 16; k4++) {
        float4 xv[4];
        #pragma unroll
        for (int i = 0; i < 4; i++)
            xv[i] = *(const float4*)&Xs[(ty * 4 + i) * 64 + k4 * 4];
        #pragma unroll
        for (int j = 0; j < 4; j++) {
            float4 w = Ws[(k4 * 4 + j) * 16 + tx];
            u64 w01 = pk2(w.x, w.y);
            u64 w23 = pk2(w.z, w.w);
            #pragma unroll
            for (int i = 0; i < 4; i++) {
                float xs = (j == 0) ? xv[i].x : (j == 1) ? xv[i].y : (j == 2) ? xv[i].z : xv[i].w;
                u64 xd = pk2(xs, xs);
                fma2(a01[i], xd, w01);
                fma2(a23[i], xd, w23);
            }
        }
    }

    float4 b = ((const float4*)bias)[tx];
    #pragma unroll
    for (int i = 0; i < 4; i++) {
        int gr = r0 + ty * 4 + i;
        if (gr >= n) continue;
        float s = g_dis[gr];
        float4 a;
        unpk2(a01[i], a.x, a.y);
        unpk2(a23[i], a.z, a.w);
        a.x = fmaxf(fmaf(s, a.x, b.x), 0.f);
        a.y = fmaxf(fmaf(s, a.y, b.y), 0.f);
        a.z = fmaxf(fmaf(s, a.z, b.z), 0.f);
        a.w = fmaxf(fmaf(s, a.w, b.w), 0.f);
        ((float4*)(out + (size_t)gr * DH))[tx] = a;
    }
}

// ---------------- fused classifier, f32x2 core --------------------------------
__global__ void k_cls(const float* __restrict__ x, const float* __restrict__ h1,
                      const float* __restrict__ y2,
                      const float* __restrict__ Wego, const float* __restrict__ bego,
                      const float* __restrict__ Wc1,  const float* __restrict__ bc1,
                      const float* __restrict__ Wcls, const float* __restrict__ bcls,
                      float* __restrict__ out, int n)
{
    __shared__ float  Xs[64 * 68];     // 17408 B
    __shared__ float4 Wcs[192 * 10];   // 30720 B

    const int tx = threadIdx.x, ty = threadIdx.y;
    const int tid = ty * 16 + tx;
    const int r0 = blockIdx.x * 64;

    const float4* Wclsv = (const float4*)Wcls;
    #pragma unroll
    for (int i = tid; i < 1920; i += 256) Wcs[i] = Wclsv[i];

    u64 c01[4], c23[4];
    #pragma unroll
    for (int i = 0; i < 4; i++) { c01[i] = 0ull; c23[i] = 0ull; }

    auto load_tile = [&](const float* S) {
        #pragma unroll
        for (int i = 0; i < 4; i++) {
            int idx = tid + i * 256;
            int rr = idx >> 4, cc = idx & 15;
            int gr = r0 + rr;
            float4 v = make_float4(0.f, 0.f, 0.f, 0.f);
            if (gr < n) v = ((const float4*)(S + (size_t)gr * DH))[cc];
            *(float4*)&Xs[rr * 68 + cc * 4] = v;
        }
    };

    auto transform = [&](const float* W, const float* bias, bool use_dis) {
        const float4* Wv = (const float4*)W;
        u64 t01[4], t23[4];
        #pragma unroll
        for (int i = 0; i < 4; i++) { t01[i] = 0ull; t23[i] = 0ull; }
        #pragma unroll
        for (int k4 = 0; k4 < 16; k4++) {
            float4 xv[4];
            #pragma unroll
            for (int i = 0; i < 4; i++)
                xv[i] = *(const float4*)&Xs[(ty * 4 + i) * 68 + k4 * 4];
            #pragma unroll
            for (int j = 0; j < 4; j++) {
                float4 w = __ldg(&Wv[(k4 * 4 + j) * 16 + tx]);
                u64 w01 = pk2(w.x, w.y);
                u64 w23 = pk2(w.z, w.w);
                #pragma unroll
                for (int i = 0; i < 4; i++) {
                    float xs = (j == 0) ? xv[i].x : (j == 1) ? xv[i].y : (j == 2) ? xv[i].z : xv[i].w;
                    u64 xd = pk2(xs, xs);
                    fma2(t01[i], xd, w01);
                    fma2(t23[i], xd, w23);
                }
            }
        }
        float4 b = __ldg(&((const float4*)bias)[tx]);
        __syncthreads();               // done reading old Xs
        #pragma unroll
        for (int i = 0; i < 4; i++) {
            int gr = r0 + ty * 4 + i;
            float s = 1.0f;
            if (use_dis) s = (gr < n) ? g_dis[gr] : 0.f;
            float4 a;
            unpk2(t01[i], a.x, a.y);
            unpk2(t23[i], a.z, a.w);
            a.x = fmaxf(fmaf(s, a.x, b.x), 0.f);
            a.y = fmaxf(fmaf(s, a.y, b.y), 0.f);
            a.z = fmaxf(fmaf(s, a.z, b.z), 0.f);
            a.w = fmaxf(fmaf(s, a.w, b.w), 0.f);
            *(float4*)&Xs[(ty * 4 + i) * 68 + tx * 4] = a;
        }
    };

    auto cls_accum = [&](int c) {
        if (tx < 10) {
            #pragma unroll
            for (int k4 = 0; k4 < 16; k4++) {
                float4 xv[4];
                #pragma unroll
                for (int i = 0; i < 4; i++)
                    xv[i] = *(const float4*)&Xs[(ty * 4 + i) * 68 + k4 * 4];
                #pragma unroll
                for (int j = 0; j < 4; j++) {
                    float4 w = Wcs[(c * 64 + k4 * 4 + j) * 10 + tx];
                    u64 w01 = pk2(w.x, w.y);
                    u64 w23 = pk2(w.z, w.w);
                    #pragma unroll
                    for (int i = 0; i < 4; i++) {
                        float xs = (j == 0) ? xv[i].x : (j == 1) ? xv[i].y : (j == 2) ? xv[i].z : xv[i].w;
                        u64 xd = pk2(xs, xs);
                        fma2(c01[i], xd, w01);
                        fma2(c23[i], xd, w23);
                    }
                }
            }
        }
    };

    // phase 0: ego = relu(x @ Wego + bego)
    load_tile(x);
    __syncthreads();
    transform(Wego, bego, false);
    __syncthreads();
    cls_accum(0);
    __syncthreads();

    // phase 1: h1 (materialized)
    load_tile(h1);
    __syncthreads();
    cls_accum(1);
    __syncthreads();

    // phase 2: h2 = relu(dis*(y2 @ Wc1) + b1)
    load_tile(y2);
    __syncthreads();
    transform(Wc1, bc1, true);
    __syncthreads();
    cls_accum(2);

    if (tx < 10) {
        float4 b = ((const float4*)bcls)[tx];
        #pragma unroll
        for (int i = 0; i < 4; i++) {
            int gr = r0 + ty * 4 + i;
            if (gr >= n) continue;
            float4 a;
            unpk2(c01[i], a.x, a.y);
            unpk2(c23[i], a.z, a.w);
            a.x += b.x; a.y += b.y; a.z += b.z; a.w += b.w;
            *(float4*)(out + (size_t)gr * CC + tx * 4) = a;
        }
    }
}

// ---------------- launch -----------------------------------------------------
extern "C" void kernel_launch(void* const* d_in, const int* in_sizes, int n_in,
                              void* d_out, int out_size)
{
    const float* x      = (const float*)d_in[0];
    const void*  ei     = d_in[1];
    const float* W_ego  = (const float*)d_in[2];
    const float* b_ego  = (const float*)d_in[3];
    const float* W_conv = (const float*)d_in[4];   // [2, 64, 64]
    const float* b_conv = (const float*)d_in[5];   // [2, 64]
    const float* W_cls  = (const float*)d_in[6];   // [192, 40]
    const float* b_cls  = (const float*)d_in[7];   // [40]

    const int N = in_sizes[0] / DH;
    const int E = in_sizes[1] / 2;

    float *y, *h1;
    cudaGetSymbolAddress((void**)&y,  g_y);
    cudaGetSymbolAddress((void**)&h1, g_h1);

    const int T = 256;
    const int NB = (N + T - 1) / T;
    const int EB = (E + T - 1) / T;
    const dim3 gb(16, 16);
    const int tile_blocks = (N + 63) / 64;
    const int agg_blocks = (int)(((long long)N * 32 + T - 1) / T);

    // ELL build + normalization (3 kernels; no count, no scan)
    k_init<<<NB, T>>>(ei, N);
    k_fill<<<EB, T>>>(ei, E);
    k_dis <<<NB, T>>>(N);

    // hop 1
    k_agg   <<<agg_blocks, T>>>(x, y, N);
    k_gemm_h<<<tile_blocks, gb>>>(y, W_conv, b_conv, h1, N);

    // hop 2
    k_agg   <<<agg_blocks, T>>>(h1, y, N);

    // fused classifier
    k_cls<<<tile_blocks, gb>>>(x, h1, y,
                               W_ego, b_ego,
                               W_conv + DH * DH, b_conv + DH,
                               W_cls, b_cls, (float*)d_out, N);
}